// round 13
// baseline (speedup 1.0000x reference)
#include <cuda_runtime.h>
#include <math.h>
#include <cstdint>

// ---------------------------------------------------------------------------
// STN fp32. R13: conv1 = Winograd F(2,3)-in-x on FFMA2 (1.5x fewer MACs;
// tensor paths closed: tcgen05 blocked by compute_103 PTX, HMMA fallback
// measured ~6x slower than FFMA2). conv3 retiled for occupancy.
// ---------------------------------------------------------------------------

__device__ __align__(16) float g_P1[16u * 127 * 127 * 16];
__device__ __align__(16) float g_P2[16u * 62 * 62 * 32];
__device__ __align__(16) float g_part[16][16][32];
__device__ __align__(16) float g_theta[16 * 6];

__constant__ float c_W2[3 * 3 * 16 * 32];
__constant__ float c_b2[32];

// ---- packed f32x2 helpers -------------------------------------------------
__device__ __forceinline__ unsigned long long pack2(float v) {
    unsigned long long r;
    asm("mov.b64 %0, {%1, %1};" : "=l"(r) : "r"(__float_as_uint(v)));
    return r;
}
__device__ __forceinline__ void ffma2(unsigned long long& a, unsigned long long v,
                                      unsigned long long w) {
    asm("fma.rn.f32x2 %0, %1, %2, %0;" : "+l"(a) : "l"(v), "l"(w));
}
__device__ __forceinline__ float2 unpack2(unsigned long long a) {
    float lo, hi;
    asm("mov.b64 {%0, %1}, %2;" : "=f"(lo), "=f"(hi) : "l"(a));
    return make_float2(lo, hi);
}

// ---------------------------------------------------------------------------
// conv1 Winograd-x: x(16,256,256,32)*W1+b1 -> relu -> pool2 -> P1(16,127,127,16)
// CTA: conv tile 16 rows x 32 cols (pooled 8x16). 256 thr = 128 slots
// (py 0..15, pxi 0..7: 1 conv row x 4 cols) x 2 cout-halves.
// smem: sWT (transformed weights) | sRaw | sInT (transformed inputs) | sPool.
// ---------------------------------------------------------------------------
static constexpr int C1_WT   = 0;                       // 3*4*32*16 f = 24576B
static constexpr int C1_RAW  = 24576;                   // 4*18*36  f = 10368B
static constexpr int C1_INT  = 24576 + 10368;           // 4*18*17*4 f = 19584B
static constexpr int C1_POOL = C1_INT + 19584;          // 16*32*16 f = 32768B
static constexpr int C1_SMEM = C1_POOL + 32768;         // 87296B

__global__ void __launch_bounds__(256, 2) conv1w_kernel(
    const float* __restrict__ x, const float* __restrict__ W,
    const float* __restrict__ bias)
{
    extern __shared__ float sm[];
    float* sWT  = sm + C1_WT / 4;
    float* sRaw = sm + C1_RAW / 4;    // [ci][row18][col36]
    float* sInT = sm + C1_INT / 4;    // [ci][row18][tile17][coef4]
    float* sPool = sm + C1_POOL / 4;  // [row16][col32][co16]

    const int t = threadIdx.x;
    const int b = blockIdx.z;
    const int R0 = blockIdx.y * 16, C0 = blockIdx.x * 32;
    const int grp = t >> 7;            // cout half
    const int slot = t & 127;
    const int py = slot >> 3, pxi = slot & 7;

    // ---- weight transform: W[ky][kx][ci][co] -> sWT[ky][coef][ci][co] ----
    for (int i = t; i < 1536; i += 256) {
        const int co = i & 15, ci = (i >> 4) & 31, ky = i >> 9;
        const float g0 = W[((ky * 3 + 0) * 32 + ci) * 16 + co];
        const float g1 = W[((ky * 3 + 1) * 32 + ci) * 16 + co];
        const float g2 = W[((ky * 3 + 2) * 32 + ci) * 16 + co];
        float* wb = sWT + ((ky * 4) * 32 + ci) * 16 + co;
        wb[0]        = g0;
        wb[32 * 16]  = 0.5f * (g0 + g1 + g2);
        wb[64 * 16]  = 0.5f * (g0 - g1 + g2);
        wb[96 * 16]  = g2;
    }

    unsigned long long acc[2][4][4];   // [tile][coef][co-u64]
#pragma unroll
    for (int u = 0; u < 2; ++u)
#pragma unroll
        for (int c = 0; c < 4; ++c)
#pragma unroll
            for (int j = 0; j < 4; ++j) acc[u][c][j] = 0ULL;

    for (int cc = 0; cc < 8; ++cc) {
        __syncthreads();
        // stage raw input rows R0..R0+17, cols C0..C0+33 (guarded)
        for (int i = t; i < 18 * 34; i += 256) {
            const int row = i / 34, col = i - 34 * (i / 34);
            const int gr = R0 + row, gc = C0 + col;
            float4 v = make_float4(0.f, 0.f, 0.f, 0.f);
            if (gr < 256 && gc < 256)
                v = *(const float4*)(x + (((size_t)(b * 256 + gr) * 256 + gc) * 32 + cc * 4));
            float* p = sRaw + row * 36 + col;
            p[0] = v.x; p[18 * 36] = v.y; p[2 * 18 * 36] = v.z; p[3 * 18 * 36] = v.w;
        }
        __syncthreads();
        // input transform: per (ci,row,tile): t0..t3 from d[2tile..2tile+3]
        for (int i = t; i < 4 * 18 * 17; i += 256) {
            const int tile = i % 17, tmp = i / 17;
            const int row = tmp % 18, ci = tmp / 18;
            const float* d = sRaw + (ci * 18 + row) * 36 + 2 * tile;
            const float d0 = d[0], d1 = d[1], d2 = d[2], d3 = d[3];
            float4 tv;
            tv.x = d0 - d2; tv.y = d1 + d2; tv.z = d2 - d1; tv.w = d1 - d3;
            *(float4*)(sInT + ((ci * 18 + row) * 17 + tile) * 4) = tv;
        }
        __syncthreads();
        // accumulate in Winograd domain
#pragma unroll
        for (int ci = 0; ci < 4; ++ci) {
#pragma unroll
            for (int ky = 0; ky < 3; ++ky) {
                const float* tb = sInT + ((ci * 18 + (py + ky)) * 17 + 2 * pxi) * 4;
                const float4 ta0 = *(const float4*)(tb);
                const float4 ta1 = *(const float4*)(tb + 4);
                unsigned long long tv0[4], tv1[4];
                tv0[0] = pack2(ta0.x); tv0[1] = pack2(ta0.y);
                tv0[2] = pack2(ta0.z); tv0[3] = pack2(ta0.w);
                tv1[0] = pack2(ta1.x); tv1[1] = pack2(ta1.y);
                tv1[2] = pack2(ta1.z); tv1[3] = pack2(ta1.w);
#pragma unroll
                for (int c = 0; c < 4; ++c) {
                    const ulonglong2* wp = (const ulonglong2*)
                        (sWT + ((ky * 4 + c) * 32 + cc * 4 + ci) * 16 + 8 * grp);
                    const ulonglong2 qa = wp[0], qb = wp[1];
                    ffma2(acc[0][c][0], tv0[c], qa.x);
                    ffma2(acc[0][c][1], tv0[c], qa.y);
                    ffma2(acc[0][c][2], tv0[c], qb.x);
                    ffma2(acc[0][c][3], tv0[c], qb.y);
                    ffma2(acc[1][c][0], tv1[c], qa.x);
                    ffma2(acc[1][c][1], tv1[c], qa.y);
                    ffma2(acc[1][c][2], tv1[c], qb.x);
                    ffma2(acc[1][c][3], tv1[c], qb.y);
                }
            }
        }
    }
    __syncthreads();

    // inverse transform: y0 = A0+A1+A2, y1 = A1-A2-A3 -> sPool[row][col][co]
#pragma unroll
    for (int u = 0; u < 2; ++u) {
        const int col = 4 * pxi + 2 * u;
        float* pp = sPool + (py * 32 + col) * 16 + 8 * grp;
#pragma unroll
        for (int j = 0; j < 4; ++j) {
            const float2 a0 = unpack2(acc[u][0][j]);
            const float2 a1 = unpack2(acc[u][1][j]);
            const float2 a2 = unpack2(acc[u][2][j]);
            const float2 a3 = unpack2(acc[u][3][j]);
            pp[2 * j]          = a0.x + a1.x + a2.x;
            pp[2 * j + 1]      = a0.y + a1.y + a2.y;
            pp[16 + 2 * j]     = a1.x - a2.x - a3.x;
            pp[16 + 2 * j + 1] = a1.y - a2.y - a3.y;
        }
    }
    __syncthreads();

    // pool 2x2 + bias + relu -> g_P1
    {
        const int q = t & 127;
        const int pr = q >> 4, pc = q & 15, h = t >> 7;
        const int gpr = blockIdx.y * 8 + pr, gpc = blockIdx.x * 16 + pc;
        if (gpr < 127 && gpc < 127) {
            const float* p00 = sPool + ((2 * pr) * 32 + 2 * pc) * 16 + 8 * h;
            const float* p10 = sPool + ((2 * pr + 1) * 32 + 2 * pc) * 16 + 8 * h;
            float* op = g_P1 + ((size_t)(b * 127 + gpr) * 127 + gpc) * 16 + 8 * h;
#pragma unroll
            for (int w = 0; w < 2; ++w) {
                const float4 v0 = ((const float4*)p00)[w];
                const float4 v1 = ((const float4*)(p00 + 16))[w];
                const float4 v2 = ((const float4*)p10)[w];
                const float4 v3 = ((const float4*)(p10 + 16))[w];
                float4 o;
                o.x = fmaxf(fmaxf(fmaxf(v0.x, v1.x), fmaxf(v2.x, v3.x)) + bias[8 * h + 4 * w],     0.f);
                o.y = fmaxf(fmaxf(fmaxf(v0.y, v1.y), fmaxf(v2.y, v3.y)) + bias[8 * h + 4 * w + 1], 0.f);
                o.z = fmaxf(fmaxf(fmaxf(v0.z, v1.z), fmaxf(v2.z, v3.z)) + bias[8 * h + 4 * w + 2], 0.f);
                o.w = fmaxf(fmaxf(fmaxf(v0.w, v1.w), fmaxf(v2.w, v3.w)) + bias[8 * h + 4 * w + 3], 0.f);
                ((float4*)op)[w] = o;
            }
        }
    }
}

// ---------------------------------------------------------------------------
// conv2: P1(16,127,127,16)*W2+b2 -> relu -> pool -> P2(16,62,62,32)  (as R4)
// ---------------------------------------------------------------------------
__global__ __launch_bounds__(256, 2) void conv2_kernel()
{
    __shared__ __align__(16) float sIn[4][18][36];
    const int b = blockIdx.z, by = blockIdx.y, bx = blockIdx.x;
    const int t = threadIdx.x;
    const int grp = t >> 6, slot = t & 63, py = slot >> 3, pxi = slot & 7;
    const int r0 = by * 16, c0 = bx * 32;

    unsigned long long acc[2][4][4];
#pragma unroll
    for (int dr = 0; dr < 2; ++dr)
#pragma unroll
        for (int dc = 0; dc < 4; ++dc)
#pragma unroll
            for (int j = 0; j < 4; ++j) acc[dr][dc][j] = 0ULL;

    for (int cc = 0; cc < 4; ++cc) {
        __syncthreads();
        for (int i = t; i < 18 * 34; i += 256) {
            int rr = i / 34, c = i - 34 * (i / 34);
            int gr = r0 + rr, gc = c0 + c;
            float4 v = make_float4(0.f, 0.f, 0.f, 0.f);
            if (gr < 127 && gc < 127)
                v = *(const float4*)(g_P1 + (((size_t)(b * 127 + gr) * 127 + gc) * 16 + cc * 4));
            sIn[0][rr][c] = v.x; sIn[1][rr][c] = v.y;
            sIn[2][rr][c] = v.z; sIn[3][rr][c] = v.w;
        }
        __syncthreads();
#pragma unroll
        for (int ci = 0; ci < 4; ++ci) {
            float v[4][6];
#pragma unroll
            for (int dr = 0; dr < 4; ++dr) {
                const float* row = &sIn[ci][2 * py + dr][4 * pxi];
                float4 f = *(const float4*)row;
                float2 g = *(const float2*)(row + 4);
                v[dr][0] = f.x; v[dr][1] = f.y; v[dr][2] = f.z;
                v[dr][3] = f.w; v[dr][4] = g.x; v[dr][5] = g.y;
            }
#pragma unroll
            for (int ky = 0; ky < 3; ++ky)
#pragma unroll
                for (int kx = 0; kx < 3; ++kx) {
                    const ulonglong2* wp = (const ulonglong2*)
                        &c_W2[(((ky * 3 + kx) * 16) + cc * 4 + ci) * 32 + 8 * grp];
                    ulonglong2 qa = wp[0], qb = wp[1];
#pragma unroll
                    for (int dr = 0; dr < 2; ++dr)
#pragma unroll
                        for (int dc = 0; dc < 4; ++dc) {
                            unsigned long long vv = pack2(v[ky + dr][kx + dc]);
                            ffma2(acc[dr][dc][0], vv, qa.x);
                            ffma2(acc[dr][dc][1], vv, qa.y);
                            ffma2(acc[dr][dc][2], vv, qb.x);
                            ffma2(acc[dr][dc][3], vv, qb.y);
                        }
                }
        }
    }

    const int ph = by * 8 + py;
#pragma unroll
    for (int s = 0; s < 2; ++s) {
        const int pw = bx * 16 + 2 * pxi + s;
        if (ph < 62 && pw < 62) {
            float* op = g_P2 + ((size_t)(b * 62 + ph) * 62 + pw) * 32 + 8 * grp;
#pragma unroll
            for (int j = 0; j < 4; ++j) {
                float2 a0 = unpack2(acc[0][2 * s][j]);
                float2 a1 = unpack2(acc[0][2 * s + 1][j]);
                float2 a2 = unpack2(acc[1][2 * s][j]);
                float2 a3 = unpack2(acc[1][2 * s + 1][j]);
                float mlo = fmaxf(fmaxf(a0.x, a1.x), fmaxf(a2.x, a3.x));
                float mhi = fmaxf(fmaxf(a0.y, a1.y), fmaxf(a2.y, a3.y));
                op[2 * j]     = fmaxf(mlo + c_b2[8 * grp + 2 * j], 0.f);
                op[2 * j + 1] = fmaxf(mhi + c_b2[8 * grp + 2 * j + 1], 0.f);
            }
        }
    }
}

// ---------------------------------------------------------------------------
// conv3: P2*W3+b3 -> relu -> pool -> per-tile channel sums (mean fused).
// Retiled: 256 CTAs (pooled 8x8), 128 thr (32 slots x 4 co-groups) -> occ 4.
// ---------------------------------------------------------------------------
__global__ __launch_bounds__(128, 4) void conv3_kernel(
    const float* __restrict__ W, const float* __restrict__ bias)
{
    __shared__ __align__(16) float sIn[4][18][20];
    __shared__ __align__(16) float sW[9 * 4 * 32];
    __shared__ float sRed[32][32];

    const int b = blockIdx.z, by = blockIdx.y, bx = blockIdx.x;
    const int t = threadIdx.x;
    const int grp = t >> 5, slot = t & 31, py = slot >> 2, pxi = slot & 3;
    const int r0 = by * 16, c0 = bx * 16;

    unsigned long long acc[2][4][4];
#pragma unroll
    for (int dr = 0; dr < 2; ++dr)
#pragma unroll
        for (int dc = 0; dc < 4; ++dc)
#pragma unroll
            for (int j = 0; j < 4; ++j) acc[dr][dc][j] = 0ULL;

    for (int cc = 0; cc < 8; ++cc) {
        __syncthreads();
        for (int i = t; i < 18 * 18; i += 128) {
            int rr = i / 18, c = i - 18 * (i / 18);
            int gr = r0 + rr, gc = c0 + c;
            float4 v = make_float4(0.f, 0.f, 0.f, 0.f);
            if (gr < 62 && gc < 62)
                v = *(const float4*)(g_P2 + (((size_t)(b * 62 + gr) * 62 + gc) * 32 + cc * 4));
            sIn[0][rr][c] = v.x; sIn[1][rr][c] = v.y;
            sIn[2][rr][c] = v.z; sIn[3][rr][c] = v.w;
        }
        for (int i = t; i < 1152; i += 128) {
            int kk = i >> 7, rem = i & 127;
            int ci = rem >> 5, co = rem & 31;
            sW[i] = W[((kk * 32) + cc * 4 + ci) * 32 + co];
        }
        __syncthreads();
#pragma unroll
        for (int ci = 0; ci < 4; ++ci) {
            float v[4][6];
#pragma unroll
            for (int dr = 0; dr < 4; ++dr) {
                const float* row = &sIn[ci][2 * py + dr][4 * pxi];
                float4 f = *(const float4*)row;
                float2 g = *(const float2*)(row + 4);
                v[dr][0] = f.x; v[dr][1] = f.y; v[dr][2] = f.z;
                v[dr][3] = f.w; v[dr][4] = g.x; v[dr][5] = g.y;
            }
#pragma unroll
            for (int ky = 0; ky < 3; ++ky)
#pragma unroll
                for (int kx = 0; kx < 3; ++kx) {
                    const ulonglong2* wp = (const ulonglong2*)
                        &sW[((ky * 3 + kx) * 4 + ci) * 32 + 8 * grp];
                    ulonglong2 qa = wp[0], qb = wp[1];
#pragma unroll
                    for (int dr = 0; dr < 2; ++dr)
#pragma unroll
                        for (int dc = 0; dc < 4; ++dc) {
                            unsigned long long vv = pack2(v[ky + dr][kx + dc]);
                            ffma2(acc[dr][dc][0], vv, qa.x);
                            ffma2(acc[dr][dc][1], vv, qa.y);
                            ffma2(acc[dr][dc][2], vv, qb.x);
                            ffma2(acc[dr][dc][3], vv, qb.y);
                        }
                }
        }
    }

    const int ph = by * 8 + py;
    float csum[8];
#pragma unroll
    for (int j = 0; j < 8; ++j) csum[j] = 0.f;
#pragma unroll
    for (int s = 0; s < 2; ++s) {
        const int pw = bx * 8 + 2 * pxi + s;
        const bool valid = (ph < 30) && (pw < 30);
#pragma unroll
        for (int j = 0; j < 4; ++j) {
            float2 a0 = unpack2(acc[0][2 * s][j]);
            float2 a1 = unpack2(acc[0][2 * s + 1][j]);
            float2 a2 = unpack2(acc[1][2 * s][j]);
            float2 a3 = unpack2(acc[1][2 * s + 1][j]);
            float mlo = fmaxf(fmaxf(a0.x, a1.x), fmaxf(a2.x, a3.x));
            float mhi = fmaxf(fmaxf(a0.y, a1.y), fmaxf(a2.y, a3.y));
            float vlo = fmaxf(mlo + bias[8 * grp + 2 * j], 0.f);
            float vhi = fmaxf(mhi + bias[8 * grp + 2 * j + 1], 0.f);
            if (valid) { csum[2 * j] += vlo; csum[2 * j + 1] += vhi; }
        }
    }
    __syncthreads();
#pragma unroll
    for (int j = 0; j < 8; ++j) sRed[slot][8 * grp + j] = csum[j];
    __syncthreads();

    if (t < 32) {
        float s = 0.f;
#pragma unroll
        for (int p = 0; p < 32; ++p) s += sRed[p][t];
        g_part[b][by * 4 + bx][t] = s;
    }
}

// ============================ head / sampler ===============================
__global__ __launch_bounds__(64) void head_kernel(
    const float* __restrict__ D1, const float* __restrict__ db1,
    const float* __restrict__ D2, const float* __restrict__ db2,
    const float* __restrict__ D3, const float* __restrict__ db3)
{
    __shared__ float h0[32], h1[64], h2[32];
    const int b = blockIdx.x, t = threadIdx.x;

    if (t < 32) {
        float s = 0.f;
#pragma unroll
        for (int tile = 0; tile < 16; ++tile) s += g_part[b][tile][t];
        h0[t] = s * (1.f / 900.f);
    }
    __syncthreads();
    {
        float a = db1[t];
#pragma unroll
        for (int k = 0; k < 32; ++k) a = fmaf(h0[k], D1[k * 64 + t], a);
        h1[t] = fmaxf(a, 0.f);
    }
    __syncthreads();
    if (t < 32) {
        float a = db2[t];
#pragma unroll
        for (int k = 0; k < 64; ++k) a = fmaf(h1[k], D2[k * 32 + t], a);
        h2[t] = fmaxf(a, 0.f);
    }
    __syncthreads();
    if (t < 6) {
        float a = db3[t];
#pragma unroll
        for (int k = 0; k < 32; ++k) a = fmaf(h2[k], D3[k * 6 + t], a);
        g_theta[b * 6 + t] = a;
    }
}

__global__ __launch_bounds__(256) void sampler_kernel(
    const float* __restrict__ x, float* __restrict__ out)
{
    __shared__ float th[6];
    const int b = blockIdx.y;
    if (threadIdx.x < 6) th[threadIdx.x] = g_theta[b * 6 + threadIdx.x];
    __syncthreads();

    const int idx = blockIdx.x * 64 + (threadIdx.x >> 2);
    const int c8 = (threadIdx.x & 3) * 8;
    const int i = idx >> 8, j = idx & 255;

    const float xs = -1.f + (float)j * (2.f / 255.f);
    const float ys = -1.f + (float)i * (2.f / 255.f);
    const float xc = th[0] * xs + th[1] * ys + th[2];
    const float yc = th[3] * xs + th[4] * ys + th[5];
    const float xf = 0.5f * ((xc + 1.0f) * 254.0f);
    const float yf = 0.5f * ((yc + 1.0f) * 254.0f);

    int x0 = (int)floorf(xf), x1 = x0 + 1;
    int y0 = (int)floorf(yf), y1 = y0 + 1;
    x0 = min(max(x0, 0), 255); x1 = min(max(x1, 0), 255);
    y0 = min(max(y0, 0), 255); y1 = min(max(y1, 0), 255);

    const float x0f = (float)x0, x1f = (float)x1;
    const float y0f = (float)y0, y1f = (float)y1;
    const float wa = (x1f - xf) * (y1f - yf);
    const float wb = (x1f - xf) * (yf - y0f);
    const float wc = (xf - x0f) * (y1f - yf);
    const float wd = (xf - x0f) * (yf - y0f);

    const float* xb = x + (size_t)b * 256 * 256 * 32;
    const float* pa = xb + ((size_t)(y0 * 256 + x0) * 32 + c8);
    const float* pb = xb + ((size_t)(y1 * 256 + x0) * 32 + c8);
    const float* pc = xb + ((size_t)(y0 * 256 + x1) * 32 + c8);
    const float* pd = xb + ((size_t)(y1 * 256 + x1) * 32 + c8);
    float* po = out + ((size_t)(b * 65536 + idx) * 32 + c8);

#pragma unroll
    for (int h = 0; h < 2; ++h) {
        const float4 Ia = __ldg((const float4*)(pa + 4 * h));
        const float4 Ib = __ldg((const float4*)(pb + 4 * h));
        const float4 Ic = __ldg((const float4*)(pc + 4 * h));
        const float4 Id = __ldg((const float4*)(pd + 4 * h));
        float4 rr;
        rr.x = wa * Ia.x + wb * Ib.x + wc * Ic.x + wd * Id.x;
        rr.y = wa * Ia.y + wb * Ib.y + wc * Ic.y + wd * Id.y;
        rr.z = wa * Ia.z + wb * Ib.z + wc * Ic.z + wd * Id.z;
        rr.w = wa * Ia.w + wb * Ib.w + wc * Ic.w + wd * Id.w;
        *(float4*)(po + 4 * h) = rr;
    }
}

// ---------------------------------------------------------------------------
extern "C" void kernel_launch(void* const* d_in, const int* in_sizes, int n_in,
                              void* d_out, int out_size)
{
    const float* x   = (const float*)d_in[0];
    const float* W1  = (const float*)d_in[1];
    const float* b1  = (const float*)d_in[2];
    const float* W3  = (const float*)d_in[5];
    const float* b3  = (const float*)d_in[6];
    const float* D1  = (const float*)d_in[7];
    const float* db1 = (const float*)d_in[8];
    const float* D2  = (const float*)d_in[9];
    const float* db2 = (const float*)d_in[10];
    const float* D3  = (const float*)d_in[11];
    const float* db3 = (const float*)d_in[12];
    float* out = (float*)d_out;

    cudaMemcpyToSymbolAsync(c_W2, d_in[3], 4608 * sizeof(float), 0,
                            cudaMemcpyDeviceToDevice, 0);
    cudaMemcpyToSymbolAsync(c_b2, d_in[4], 32 * sizeof(float), 0,
                            cudaMemcpyDeviceToDevice, 0);

    cudaFuncSetAttribute(conv1w_kernel,
                         cudaFuncAttributeMaxDynamicSharedMemorySize, C1_SMEM);

    conv1w_kernel<<<dim3(8, 16, 16), 256, C1_SMEM>>>(x, W1, b1);
    conv2_kernel<<<dim3(4, 8, 16), 256>>>();
    conv3_kernel<<<dim3(4, 4, 16), 128>>>(W3, b3);
    head_kernel<<<16, 64>>>(D1, db1, D2, db2, D3, db3);
    sampler_kernel<<<dim3(1024, 16), 256>>>(x, out);
}

// round 14
// speedup vs baseline: 1.0202x; 1.0202x over previous
#include <cuda_runtime.h>
#include <math.h>
#include <cstdint>

// ---------------------------------------------------------------------------
// STN fp32. R14: Winograd F(2,3)-in-x conv1, spill-proofed (one-tile inner
// loop, ~94 live regs) + smem 57KB (sPool unioned over sRaw/sInT).
// conv2 FFMA2+const, conv3 retiled (proven R13), head/sampler unchanged.
// ---------------------------------------------------------------------------

__device__ __align__(16) float g_P1[16u * 127 * 127 * 16];
__device__ __align__(16) float g_P2[16u * 62 * 62 * 32];
__device__ __align__(16) float g_part[16][16][32];
__device__ __align__(16) float g_theta[16 * 6];

__constant__ float c_W2[3 * 3 * 16 * 32];
__constant__ float c_b2[32];

// ---- packed f32x2 helpers -------------------------------------------------
__device__ __forceinline__ unsigned long long pack2(float v) {
    unsigned long long r;
    asm("mov.b64 %0, {%1, %1};" : "=l"(r) : "r"(__float_as_uint(v)));
    return r;
}
__device__ __forceinline__ void ffma2(unsigned long long& a, unsigned long long v,
                                      unsigned long long w) {
    asm("fma.rn.f32x2 %0, %1, %2, %0;" : "+l"(a) : "l"(v), "l"(w));
}
__device__ __forceinline__ float2 unpack2(unsigned long long a) {
    float lo, hi;
    asm("mov.b64 {%0, %1}, %2;" : "=f"(lo), "=f"(hi) : "l"(a));
    return make_float2(lo, hi);
}

// ---------------------------------------------------------------------------
// conv1 Winograd-x. CTA: conv tile 16 rows x 32 cols (pooled 8x16).
// 256 thr = 128 slots (py 0..15 x tile-pair pxi 0..7) x 2 cout-halves.
// smem: sWT(24576B) | union{ sRaw(10368)+sInT(19584) , sPool(32768) } = 57344B
// ---------------------------------------------------------------------------
static constexpr int C1_SMEM = 57344;

__global__ void __launch_bounds__(256, 2) conv1w_kernel(
    const float* __restrict__ x, const float* __restrict__ W,
    const float* __restrict__ bias)
{
    extern __shared__ float sm[];
    float* sWT   = sm;               // [ky][coef][ci32][co16]  6144 f
    float* sRaw  = sm + 6144;        // [ci][row18][col36]      2592 f
    float* sInT  = sm + 6144 + 2592; // [ci][row18][tile17][4]  4896 f
    float* sPool = sm + 6144;        // [row16][col32][co16]    8192 f (after)

    const int t = threadIdx.x;
    const int b = blockIdx.z;
    const int R0 = blockIdx.y * 16, C0 = blockIdx.x * 32;
    const int grp = t >> 7;
    const int slot = t & 127;
    const int py = slot >> 3, pxi = slot & 7;

    // weight transform: W[ky][kx][ci][co] -> sWT[ky][coef][ci][co]
    for (int i = t; i < 1536; i += 256) {
        const int co = i & 15, ci = (i >> 4) & 31, ky = i >> 9;
        const float g0 = W[((ky * 3 + 0) * 32 + ci) * 16 + co];
        const float g1 = W[((ky * 3 + 1) * 32 + ci) * 16 + co];
        const float g2 = W[((ky * 3 + 2) * 32 + ci) * 16 + co];
        float* wb = sWT + ((ky * 4) * 32 + ci) * 16 + co;
        wb[0]       = g0;
        wb[32 * 16] = 0.5f * (g0 + g1 + g2);
        wb[64 * 16] = 0.5f * (g0 - g1 + g2);
        wb[96 * 16] = g2;
    }

    unsigned long long acc[2][4][4];   // [tile][coef][co-u64]
#pragma unroll
    for (int u = 0; u < 2; ++u)
#pragma unroll
        for (int c = 0; c < 4; ++c)
#pragma unroll
            for (int j = 0; j < 4; ++j) acc[u][c][j] = 0ULL;

    for (int cc = 0; cc < 8; ++cc) {
        __syncthreads();
        // stage raw rows R0..R0+17, cols C0..C0+33 (guarded, coalesced LDG)
        for (int i = t; i < 18 * 34; i += 256) {
            const int row = i / 34, col = i - 34 * (i / 34);
            const int gr = R0 + row, gc = C0 + col;
            float4 v = make_float4(0.f, 0.f, 0.f, 0.f);
            if (gr < 256 && gc < 256)
                v = *(const float4*)(x + (((size_t)(b * 256 + gr) * 256 + gc) * 32 + cc * 4));
            float* p = sRaw + row * 36 + col;
            p[0] = v.x; p[18 * 36] = v.y; p[2 * 18 * 36] = v.z; p[3 * 18 * 36] = v.w;
        }
        __syncthreads();
        // x-transform per (ci,row,tile)
        for (int i = t; i < 4 * 18 * 17; i += 256) {
            const int tile = i % 17, tmp = i / 17;
            const int row = tmp % 18, ci = tmp / 18;
            const float* d = sRaw + (ci * 18 + row) * 36 + 2 * tile;
            const float d0 = d[0], d1 = d[1], d2 = d[2], d3 = d[3];
            float4 tv;
            tv.x = d0 - d2; tv.y = d1 + d2; tv.z = d2 - d1; tv.w = d1 - d3;
            *(float4*)(sInT + ((ci * 18 + row) * 17 + tile) * 4) = tv;
        }
        __syncthreads();
        // accumulate (one tile at a time -> low live-register count)
#pragma unroll
        for (int ci = 0; ci < 4; ++ci) {
#pragma unroll
            for (int ky = 0; ky < 3; ++ky) {
                const float* tb = sInT + ((ci * 18 + (py + ky)) * 17 + 2 * pxi) * 4;
#pragma unroll
                for (int u = 0; u < 2; ++u) {
                    const float4 ta = *(const float4*)(tb + 4 * u);
                    unsigned long long tv0 = pack2(ta.x);
                    unsigned long long tv1 = pack2(ta.y);
                    unsigned long long tv2 = pack2(ta.z);
                    unsigned long long tv3 = pack2(ta.w);
#pragma unroll
                    for (int c = 0; c < 4; ++c) {
                        const unsigned long long tv =
                            (c == 0) ? tv0 : (c == 1) ? tv1 : (c == 2) ? tv2 : tv3;
                        const ulonglong2* wp = (const ulonglong2*)
                            (sWT + ((ky * 4 + c) * 32 + cc * 4 + ci) * 16 + 8 * grp);
                        const ulonglong2 qa = wp[0], qb = wp[1];
                        ffma2(acc[u][c][0], tv, qa.x);
                        ffma2(acc[u][c][1], tv, qa.y);
                        ffma2(acc[u][c][2], tv, qb.x);
                        ffma2(acc[u][c][3], tv, qb.y);
                    }
                }
            }
        }
    }
    __syncthreads();   // sRaw/sInT dead; sPool takes over the union region

    // inverse transform: y0 = A0+A1+A2, y1 = A1-A2-A3
#pragma unroll
    for (int u = 0; u < 2; ++u) {
        const int col = 4 * pxi + 2 * u;
        float* pp = sPool + (py * 32 + col) * 16 + 8 * grp;
#pragma unroll
        for (int j = 0; j < 4; ++j) {
            const float2 a0 = unpack2(acc[u][0][j]);
            const float2 a1 = unpack2(acc[u][1][j]);
            const float2 a2 = unpack2(acc[u][2][j]);
            const float2 a3 = unpack2(acc[u][3][j]);
            pp[2 * j]          = a0.x + a1.x + a2.x;
            pp[2 * j + 1]      = a0.y + a1.y + a2.y;
            pp[16 + 2 * j]     = a1.x - a2.x - a3.x;
            pp[16 + 2 * j + 1] = a1.y - a2.y - a3.y;
        }
    }
    __syncthreads();

    // 2x2 maxpool + bias + relu -> g_P1
    {
        const int q = t & 127;
        const int pr = q >> 4, pc = q & 15, h = t >> 7;
        const int gpr = blockIdx.y * 8 + pr, gpc = blockIdx.x * 16 + pc;
        if (gpr < 127 && gpc < 127) {
            const float* p00 = sPool + ((2 * pr) * 32 + 2 * pc) * 16 + 8 * h;
            const float* p10 = sPool + ((2 * pr + 1) * 32 + 2 * pc) * 16 + 8 * h;
            float* op = g_P1 + ((size_t)(b * 127 + gpr) * 127 + gpc) * 16 + 8 * h;
#pragma unroll
            for (int w = 0; w < 2; ++w) {
                const float4 v0 = ((const float4*)p00)[w];
                const float4 v1 = ((const float4*)(p00 + 16))[w];
                const float4 v2 = ((const float4*)p10)[w];
                const float4 v3 = ((const float4*)(p10 + 16))[w];
                float4 o;
                o.x = fmaxf(fmaxf(fmaxf(v0.x, v1.x), fmaxf(v2.x, v3.x)) + bias[8 * h + 4 * w],     0.f);
                o.y = fmaxf(fmaxf(fmaxf(v0.y, v1.y), fmaxf(v2.y, v3.y)) + bias[8 * h + 4 * w + 1], 0.f);
                o.z = fmaxf(fmaxf(fmaxf(v0.z, v1.z), fmaxf(v2.z, v3.z)) + bias[8 * h + 4 * w + 2], 0.f);
                o.w = fmaxf(fmaxf(fmaxf(v0.w, v1.w), fmaxf(v2.w, v3.w)) + bias[8 * h + 4 * w + 3], 0.f);
                ((float4*)op)[w] = o;
            }
        }
    }
}

// ---------------------------------------------------------------------------
// conv2: P1*W2+b2 -> relu -> pool -> P2 (R4 structure, proven)
// ---------------------------------------------------------------------------
__global__ __launch_bounds__(256, 2) void conv2_kernel()
{
    __shared__ __align__(16) float sIn[4][18][36];
    const int b = blockIdx.z, by = blockIdx.y, bx = blockIdx.x;
    const int t = threadIdx.x;
    const int grp = t >> 6, slot = t & 63, py = slot >> 3, pxi = slot & 7;
    const int r0 = by * 16, c0 = bx * 32;

    unsigned long long acc[2][4][4];
#pragma unroll
    for (int dr = 0; dr < 2; ++dr)
#pragma unroll
        for (int dc = 0; dc < 4; ++dc)
#pragma unroll
            for (int j = 0; j < 4; ++j) acc[dr][dc][j] = 0ULL;

    for (int cc = 0; cc < 4; ++cc) {
        __syncthreads();
        for (int i = t; i < 18 * 34; i += 256) {
            int rr = i / 34, c = i - 34 * (i / 34);
            int gr = r0 + rr, gc = c0 + c;
            float4 v = make_float4(0.f, 0.f, 0.f, 0.f);
            if (gr < 127 && gc < 127)
                v = *(const float4*)(g_P1 + (((size_t)(b * 127 + gr) * 127 + gc) * 16 + cc * 4));
            sIn[0][rr][c] = v.x; sIn[1][rr][c] = v.y;
            sIn[2][rr][c] = v.z; sIn[3][rr][c] = v.w;
        }
        __syncthreads();
#pragma unroll
        for (int ci = 0; ci < 4; ++ci) {
            float v[4][6];
#pragma unroll
            for (int dr = 0; dr < 4; ++dr) {
                const float* row = &sIn[ci][2 * py + dr][4 * pxi];
                float4 f = *(const float4*)row;
                float2 g = *(const float2*)(row + 4);
                v[dr][0] = f.x; v[dr][1] = f.y; v[dr][2] = f.z;
                v[dr][3] = f.w; v[dr][4] = g.x; v[dr][5] = g.y;
            }
#pragma unroll
            for (int ky = 0; ky < 3; ++ky)
#pragma unroll
                for (int kx = 0; kx < 3; ++kx) {
                    const ulonglong2* wp = (const ulonglong2*)
                        &c_W2[(((ky * 3 + kx) * 16) + cc * 4 + ci) * 32 + 8 * grp];
                    ulonglong2 qa = wp[0], qb = wp[1];
#pragma unroll
                    for (int dr = 0; dr < 2; ++dr)
#pragma unroll
                        for (int dc = 0; dc < 4; ++dc) {
                            unsigned long long vv = pack2(v[ky + dr][kx + dc]);
                            ffma2(acc[dr][dc][0], vv, qa.x);
                            ffma2(acc[dr][dc][1], vv, qa.y);
                            ffma2(acc[dr][dc][2], vv, qb.x);
                            ffma2(acc[dr][dc][3], vv, qb.y);
                        }
                }
        }
    }

    const int ph = by * 8 + py;
#pragma unroll
    for (int s = 0; s < 2; ++s) {
        const int pw = bx * 16 + 2 * pxi + s;
        if (ph < 62 && pw < 62) {
            float* op = g_P2 + ((size_t)(b * 62 + ph) * 62 + pw) * 32 + 8 * grp;
#pragma unroll
            for (int j = 0; j < 4; ++j) {
                float2 a0 = unpack2(acc[0][2 * s][j]);
                float2 a1 = unpack2(acc[0][2 * s + 1][j]);
                float2 a2 = unpack2(acc[1][2 * s][j]);
                float2 a3 = unpack2(acc[1][2 * s + 1][j]);
                float mlo = fmaxf(fmaxf(a0.x, a1.x), fmaxf(a2.x, a3.x));
                float mhi = fmaxf(fmaxf(a0.y, a1.y), fmaxf(a2.y, a3.y));
                op[2 * j]     = fmaxf(mlo + c_b2[8 * grp + 2 * j], 0.f);
                op[2 * j + 1] = fmaxf(mhi + c_b2[8 * grp + 2 * j + 1], 0.f);
            }
        }
    }
}

// ---------------------------------------------------------------------------
// conv3: retiled 128 thr / occ 4 (proven in R13 run), mean fused.
// ---------------------------------------------------------------------------
__global__ __launch_bounds__(128, 4) void conv3_kernel(
    const float* __restrict__ W, const float* __restrict__ bias)
{
    __shared__ __align__(16) float sIn[4][18][20];
    __shared__ __align__(16) float sW[9 * 4 * 32];
    __shared__ float sRed[32][32];

    const int b = blockIdx.z, by = blockIdx.y, bx = blockIdx.x;
    const int t = threadIdx.x;
    const int grp = t >> 5, slot = t & 31, py = slot >> 2, pxi = slot & 3;
    const int r0 = by * 16, c0 = bx * 16;

    unsigned long long acc[2][4][4];
#pragma unroll
    for (int dr = 0; dr < 2; ++dr)
#pragma unroll
        for (int dc = 0; dc < 4; ++dc)
#pragma unroll
            for (int j = 0; j < 4; ++j) acc[dr][dc][j] = 0ULL;

    for (int cc = 0; cc < 8; ++cc) {
        __syncthreads();
        for (int i = t; i < 18 * 18; i += 128) {
            int rr = i / 18, c = i - 18 * (i / 18);
            int gr = r0 + rr, gc = c0 + c;
            float4 v = make_float4(0.f, 0.f, 0.f, 0.f);
            if (gr < 62 && gc < 62)
                v = *(const float4*)(g_P2 + (((size_t)(b * 62 + gr) * 62 + gc) * 32 + cc * 4));
            sIn[0][rr][c] = v.x; sIn[1][rr][c] = v.y;
            sIn[2][rr][c] = v.z; sIn[3][rr][c] = v.w;
        }
        for (int i = t; i < 1152; i += 128) {
            int kk = i >> 7, rem = i & 127;
            int ci = rem >> 5, co = rem & 31;
            sW[i] = W[((kk * 32) + cc * 4 + ci) * 32 + co];
        }
        __syncthreads();
#pragma unroll
        for (int ci = 0; ci < 4; ++ci) {
            float v[4][6];
#pragma unroll
            for (int dr = 0; dr < 4; ++dr) {
                const float* row = &sIn[ci][2 * py + dr][4 * pxi];
                float4 f = *(const float4*)row;
                float2 g = *(const float2*)(row + 4);
                v[dr][0] = f.x; v[dr][1] = f.y; v[dr][2] = f.z;
                v[dr][3] = f.w; v[dr][4] = g.x; v[dr][5] = g.y;
            }
#pragma unroll
            for (int ky = 0; ky < 3; ++ky)
#pragma unroll
                for (int kx = 0; kx < 3; ++kx) {
                    const ulonglong2* wp = (const ulonglong2*)
                        &sW[((ky * 3 + kx) * 4 + ci) * 32 + 8 * grp];
                    ulonglong2 qa = wp[0], qb = wp[1];
#pragma unroll
                    for (int dr = 0; dr < 2; ++dr)
#pragma unroll
                        for (int dc = 0; dc < 4; ++dc) {
                            unsigned long long vv = pack2(v[ky + dr][kx + dc]);
                            ffma2(acc[dr][dc][0], vv, qa.x);
                            ffma2(acc[dr][dc][1], vv, qa.y);
                            ffma2(acc[dr][dc][2], vv, qb.x);
                            ffma2(acc[dr][dc][3], vv, qb.y);
                        }
                }
        }
    }

    const int ph = by * 8 + py;
    float csum[8];
#pragma unroll
    for (int j = 0; j < 8; ++j) csum[j] = 0.f;
#pragma unroll
    for (int s = 0; s < 2; ++s) {
        const int pw = bx * 8 + 2 * pxi + s;
        const bool valid = (ph < 30) && (pw < 30);
#pragma unroll
        for (int j = 0; j < 4; ++j) {
            float2 a0 = unpack2(acc[0][2 * s][j]);
            float2 a1 = unpack2(acc[0][2 * s + 1][j]);
            float2 a2 = unpack2(acc[1][2 * s][j]);
            float2 a3 = unpack2(acc[1][2 * s + 1][j]);
            float mlo = fmaxf(fmaxf(a0.x, a1.x), fmaxf(a2.x, a3.x));
            float mhi = fmaxf(fmaxf(a0.y, a1.y), fmaxf(a2.y, a3.y));
            float vlo = fmaxf(mlo + bias[8 * grp + 2 * j], 0.f);
            float vhi = fmaxf(mhi + bias[8 * grp + 2 * j + 1], 0.f);
            if (valid) { csum[2 * j] += vlo; csum[2 * j + 1] += vhi; }
        }
    }
    __syncthreads();
#pragma unroll
    for (int j = 0; j < 8; ++j) sRed[slot][8 * grp + j] = csum[j];
    __syncthreads();

    if (t < 32) {
        float s = 0.f;
#pragma unroll
        for (int p = 0; p < 32; ++p) s += sRed[p][t];
        g_part[b][by * 4 + bx][t] = s;
    }
}

// ============================ head / sampler ===============================
__global__ __launch_bounds__(64) void head_kernel(
    const float* __restrict__ D1, const float* __restrict__ db1,
    const float* __restrict__ D2, const float* __restrict__ db2,
    const float* __restrict__ D3, const float* __restrict__ db3)
{
    __shared__ float h0[32], h1[64], h2[32];
    const int b = blockIdx.x, t = threadIdx.x;

    if (t < 32) {
        float s = 0.f;
#pragma unroll
        for (int tile = 0; tile < 16; ++tile) s += g_part[b][tile][t];
        h0[t] = s * (1.f / 900.f);
    }
    __syncthreads();
    {
        float a = db1[t];
#pragma unroll
        for (int k = 0; k < 32; ++k) a = fmaf(h0[k], D1[k * 64 + t], a);
        h1[t] = fmaxf(a, 0.f);
    }
    __syncthreads();
    if (t < 32) {
        float a = db2[t];
#pragma unroll
        for (int k = 0; k < 64; ++k) a = fmaf(h1[k], D2[k * 32 + t], a);
        h2[t] = fmaxf(a, 0.f);
    }
    __syncthreads();
    if (t < 6) {
        float a = db3[t];
#pragma unroll
        for (int k = 0; k < 32; ++k) a = fmaf(h2[k], D3[k * 6 + t], a);
        g_theta[b * 6 + t] = a;
    }
}

__global__ __launch_bounds__(256) void sampler_kernel(
    const float* __restrict__ x, float* __restrict__ out)
{
    __shared__ float th[6];
    const int b = blockIdx.y;
    if (threadIdx.x < 6) th[threadIdx.x] = g_theta[b * 6 + threadIdx.x];
    __syncthreads();

    const int idx = blockIdx.x * 64 + (threadIdx.x >> 2);
    const int c8 = (threadIdx.x & 3) * 8;
    const int i = idx >> 8, j = idx & 255;

    const float xs = -1.f + (float)j * (2.f / 255.f);
    const float ys = -1.f + (float)i * (2.f / 255.f);
    const float xc = th[0] * xs + th[1] * ys + th[2];
    const float yc = th[3] * xs + th[4] * ys + th[5];
    const float xf = 0.5f * ((xc + 1.0f) * 254.0f);
    const float yf = 0.5f * ((yc + 1.0f) * 254.0f);

    int x0 = (int)floorf(xf), x1 = x0 + 1;
    int y0 = (int)floorf(yf), y1 = y0 + 1;
    x0 = min(max(x0, 0), 255); x1 = min(max(x1, 0), 255);
    y0 = min(max(y0, 0), 255); y1 = min(max(y1, 0), 255);

    const float x0f = (float)x0, x1f = (float)x1;
    const float y0f = (float)y0, y1f = (float)y1;
    const float wa = (x1f - xf) * (y1f - yf);
    const float wb = (x1f - xf) * (yf - y0f);
    const float wc = (xf - x0f) * (y1f - yf);
    const float wd = (xf - x0f) * (yf - y0f);

    const float* xb = x + (size_t)b * 256 * 256 * 32;
    const float* pa = xb + ((size_t)(y0 * 256 + x0) * 32 + c8);
    const float* pb = xb + ((size_t)(y1 * 256 + x0) * 32 + c8);
    const float* pc = xb + ((size_t)(y0 * 256 + x1) * 32 + c8);
    const float* pd = xb + ((size_t)(y1 * 256 + x1) * 32 + c8);
    float* po = out + ((size_t)(b * 65536 + idx) * 32 + c8);

#pragma unroll
    for (int h = 0; h < 2; ++h) {
        const float4 Ia = __ldg((const float4*)(pa + 4 * h));
        const float4 Ib = __ldg((const float4*)(pb + 4 * h));
        const float4 Ic = __ldg((const float4*)(pc + 4 * h));
        const float4 Id = __ldg((const float4*)(pd + 4 * h));
        float4 rr;
        rr.x = wa * Ia.x + wb * Ib.x + wc * Ic.x + wd * Id.x;
        rr.y = wa * Ia.y + wb * Ib.y + wc * Ic.y + wd * Id.y;
        rr.z = wa * Ia.z + wb * Ib.z + wc * Ic.z + wd * Id.z;
        rr.w = wa * Ia.w + wb * Ib.w + wc * Ic.w + wd * Id.w;
        *(float4*)(po + 4 * h) = rr;
    }
}

// ---------------------------------------------------------------------------
extern "C" void kernel_launch(void* const* d_in, const int* in_sizes, int n_in,
                              void* d_out, int out_size)
{
    const float* x   = (const float*)d_in[0];
    const float* W1  = (const float*)d_in[1];
    const float* b1  = (const float*)d_in[2];
    const float* W3  = (const float*)d_in[5];
    const float* b3  = (const float*)d_in[6];
    const float* D1  = (const float*)d_in[7];
    const float* db1 = (const float*)d_in[8];
    const float* D2  = (const float*)d_in[9];
    const float* db2 = (const float*)d_in[10];
    const float* D3  = (const float*)d_in[11];
    const float* db3 = (const float*)d_in[12];
    float* out = (float*)d_out;

    cudaMemcpyToSymbolAsync(c_W2, d_in[3], 4608 * sizeof(float), 0,
                            cudaMemcpyDeviceToDevice, 0);
    cudaMemcpyToSymbolAsync(c_b2, d_in[4], 32 * sizeof(float), 0,
                            cudaMemcpyDeviceToDevice, 0);

    cudaFuncSetAttribute(conv1w_kernel,
                         cudaFuncAttributeMaxDynamicSharedMemorySize, C1_SMEM);

    conv1w_kernel<<<dim3(8, 16, 16), 256, C1_SMEM>>>(x, W1, b1);
    conv2_kernel<<<dim3(4, 8, 16), 256>>>();
    conv3_kernel<<<dim3(4, 4, 16), 128>>>(W3, b3);
    head_kernel<<<16, 64>>>(D1, db1, D2, db2, D3, db3);
    sampler_kernel<<<dim3(1024, 16), 256>>>(x, out);
}

// round 15
// speedup vs baseline: 1.6993x; 1.6657x over previous
#include <cuda_runtime.h>
#include <math.h>
#include <cstdint>

// ---------------------------------------------------------------------------
// STN fp32 on FFMA2 (rt=3 banking ceiling is the wall; tensor paths closed:
// tcgen05 blocked by compute_103 PTX, HMMA fallback 6x slower, Winograd
// formulation 3x over floor twice -> reverted). R15 = proven R5 conv1/conv2
// + R13 conv3 retile (fixes measured 47us -> ~30us occupancy problem).
// ---------------------------------------------------------------------------

__device__ __align__(16) float g_P1[16u * 127 * 127 * 16];
__device__ __align__(16) float g_P2[16u * 62 * 62 * 32];
__device__ __align__(16) float g_part[16][16][32];
__device__ __align__(16) float g_theta[16 * 6];

__constant__ float c_W1[3 * 3 * 32 * 16];
__constant__ float c_b1[16];
__constant__ float c_W2[3 * 3 * 16 * 32];
__constant__ float c_b2[32];

// ---- packed f32x2 helpers (FFMA2: PTX-only, ptxas never emits) ------------
__device__ __forceinline__ unsigned long long pack2(float v) {
    unsigned long long r;
    asm("mov.b64 %0, {%1, %1};" : "=l"(r) : "r"(__float_as_uint(v)));
    return r;
}
__device__ __forceinline__ void ffma2(unsigned long long& a, unsigned long long v,
                                      unsigned long long w) {
    asm("fma.rn.f32x2 %0, %1, %2, %0;" : "+l"(a) : "l"(v), "l"(w));
}
__device__ __forceinline__ float2 unpack2(unsigned long long a) {
    float lo, hi;
    asm("mov.b64 {%0, %1}, %2;" : "=f"(lo), "=f"(hi) : "l"(a));
    return make_float2(lo, hi);
}

// ---------------------------------------------------------------------------
// conv1: x(16,256,256,32)*W1+b1 -> relu -> pool2 -> P1(16,127,127,16)
// Proven 198us (at FFMA2 floor). 256 thr = 128 slots x 2 cout-groups.
// ---------------------------------------------------------------------------
__global__ __launch_bounds__(256, 2) void conv1_kernel(const float* __restrict__ x)
{
    __shared__ __align__(16) float sIn[4][34][36];

    const int b  = blockIdx.z;
    const int by = blockIdx.y, bx = blockIdx.x;
    const int t  = threadIdx.x;
    const int grp  = t >> 7;
    const int slot = t & 127;
    const int py   = slot >> 3;
    const int pxi  = slot & 7;
    const int r0 = by * 32, c0 = bx * 32;

    unsigned long long acc[2][4][4];
#pragma unroll
    for (int dr = 0; dr < 2; ++dr)
#pragma unroll
        for (int dc = 0; dc < 4; ++dc)
#pragma unroll
            for (int j = 0; j < 4; ++j) acc[dr][dc][j] = 0ULL;

    for (int cc = 0; cc < 8; ++cc) {
        __syncthreads();
        for (int i = t; i < 34 * 34; i += 256) {
            int r = i / 34, c = i - 34 * (i / 34);
            int gr = r0 + r, gc = c0 + c;
            float4 v = make_float4(0.f, 0.f, 0.f, 0.f);
            if (gr < 256 && gc < 256)
                v = *(const float4*)(x + (((size_t)(b * 256 + gr) * 256 + gc) * 32 + cc * 4));
            sIn[0][r][c] = v.x; sIn[1][r][c] = v.y;
            sIn[2][r][c] = v.z; sIn[3][r][c] = v.w;
        }
        __syncthreads();

#pragma unroll
        for (int ci = 0; ci < 4; ++ci) {
            float v[4][6];
#pragma unroll
            for (int dr = 0; dr < 4; ++dr) {
                const float* row = &sIn[ci][2 * py + dr][4 * pxi];
                float4 f = *(const float4*)row;
                float2 g = *(const float2*)(row + 4);
                v[dr][0] = f.x; v[dr][1] = f.y; v[dr][2] = f.z;
                v[dr][3] = f.w; v[dr][4] = g.x; v[dr][5] = g.y;
            }
#pragma unroll
            for (int ky = 0; ky < 3; ++ky)
#pragma unroll
                for (int kx = 0; kx < 3; ++kx) {
                    const ulonglong2* wp = (const ulonglong2*)
                        &c_W1[(((ky * 3 + kx) * 32) + cc * 4 + ci) * 16 + 8 * grp];
                    ulonglong2 qa = wp[0], qb = wp[1];
#pragma unroll
                    for (int dr = 0; dr < 2; ++dr)
#pragma unroll
                        for (int dc = 0; dc < 4; ++dc) {
                            unsigned long long vv = pack2(v[ky + dr][kx + dc]);
                            ffma2(acc[dr][dc][0], vv, qa.x);
                            ffma2(acc[dr][dc][1], vv, qa.y);
                            ffma2(acc[dr][dc][2], vv, qb.x);
                            ffma2(acc[dr][dc][3], vv, qb.y);
                        }
                }
        }
    }

    const int ph = by * 16 + py;
#pragma unroll
    for (int s = 0; s < 2; ++s) {
        const int pw = bx * 16 + 2 * pxi + s;
        if (ph < 127 && pw < 127) {
            float* op = g_P1 + ((size_t)(b * 127 + ph) * 127 + pw) * 16 + 8 * grp;
#pragma unroll
            for (int j = 0; j < 4; ++j) {
                float2 a0 = unpack2(acc[0][2 * s][j]);
                float2 a1 = unpack2(acc[0][2 * s + 1][j]);
                float2 a2 = unpack2(acc[1][2 * s][j]);
                float2 a3 = unpack2(acc[1][2 * s + 1][j]);
                float mlo = fmaxf(fmaxf(a0.x, a1.x), fmaxf(a2.x, a3.x));
                float mhi = fmaxf(fmaxf(a0.y, a1.y), fmaxf(a2.y, a3.y));
                op[2 * j]     = fmaxf(mlo + c_b1[8 * grp + 2 * j], 0.f);
                op[2 * j + 1] = fmaxf(mhi + c_b1[8 * grp + 2 * j + 1], 0.f);
            }
        }
    }
}

// ---------------------------------------------------------------------------
// conv2: P1*W2+b2 -> relu -> pool -> P2 (proven 48us, at floor)
// ---------------------------------------------------------------------------
__global__ __launch_bounds__(256, 2) void conv2_kernel()
{
    __shared__ __align__(16) float sIn[4][18][36];

    const int b  = blockIdx.z;
    const int by = blockIdx.y, bx = blockIdx.x;
    const int t  = threadIdx.x;
    const int grp  = t >> 6;
    const int slot = t & 63;
    const int py   = slot >> 3;
    const int pxi  = slot & 7;
    const int r0 = by * 16, c0 = bx * 32;

    unsigned long long acc[2][4][4];
#pragma unroll
    for (int dr = 0; dr < 2; ++dr)
#pragma unroll
        for (int dc = 0; dc < 4; ++dc)
#pragma unroll
            for (int j = 0; j < 4; ++j) acc[dr][dc][j] = 0ULL;

    for (int cc = 0; cc < 4; ++cc) {
        __syncthreads();
        for (int i = t; i < 18 * 34; i += 256) {
            int r = i / 34, c = i - 34 * (i / 34);
            int gr = r0 + r, gc = c0 + c;
            float4 v = make_float4(0.f, 0.f, 0.f, 0.f);
            if (gr < 127 && gc < 127)
                v = *(const float4*)(g_P1 + (((size_t)(b * 127 + gr) * 127 + gc) * 16 + cc * 4));
            sIn[0][r][c] = v.x; sIn[1][r][c] = v.y;
            sIn[2][r][c] = v.z; sIn[3][r][c] = v.w;
        }
        __syncthreads();

#pragma unroll
        for (int ci = 0; ci < 4; ++ci) {
            float v[4][6];
#pragma unroll
            for (int dr = 0; dr < 4; ++dr) {
                const float* row = &sIn[ci][2 * py + dr][4 * pxi];
                float4 f = *(const float4*)row;
                float2 g = *(const float2*)(row + 4);
                v[dr][0] = f.x; v[dr][1] = f.y; v[dr][2] = f.z;
                v[dr][3] = f.w; v[dr][4] = g.x; v[dr][5] = g.y;
            }
#pragma unroll
            for (int ky = 0; ky < 3; ++ky)
#pragma unroll
                for (int kx = 0; kx < 3; ++kx) {
                    const ulonglong2* wp = (const ulonglong2*)
                        &c_W2[(((ky * 3 + kx) * 16) + cc * 4 + ci) * 32 + 8 * grp];
                    ulonglong2 qa = wp[0], qb = wp[1];
#pragma unroll
                    for (int dr = 0; dr < 2; ++dr)
#pragma unroll
                        for (int dc = 0; dc < 4; ++dc) {
                            unsigned long long vv = pack2(v[ky + dr][kx + dc]);
                            ffma2(acc[dr][dc][0], vv, qa.x);
                            ffma2(acc[dr][dc][1], vv, qa.y);
                            ffma2(acc[dr][dc][2], vv, qb.x);
                            ffma2(acc[dr][dc][3], vv, qb.y);
                        }
                }
        }
    }

    const int ph = by * 8 + py;
#pragma unroll
    for (int s = 0; s < 2; ++s) {
        const int pw = bx * 16 + 2 * pxi + s;
        if (ph < 62 && pw < 62) {
            float* op = g_P2 + ((size_t)(b * 62 + ph) * 62 + pw) * 32 + 8 * grp;
#pragma unroll
            for (int j = 0; j < 4; ++j) {
                float2 a0 = unpack2(acc[0][2 * s][j]);
                float2 a1 = unpack2(acc[0][2 * s + 1][j]);
                float2 a2 = unpack2(acc[1][2 * s][j]);
                float2 a3 = unpack2(acc[1][2 * s + 1][j]);
                float mlo = fmaxf(fmaxf(a0.x, a1.x), fmaxf(a2.x, a3.x));
                float mhi = fmaxf(fmaxf(a0.y, a1.y), fmaxf(a2.y, a3.y));
                op[2 * j]     = fmaxf(mlo + c_b2[8 * grp + 2 * j], 0.f);
                op[2 * j + 1] = fmaxf(mhi + c_b2[8 * grp + 2 * j + 1], 0.f);
            }
        }
    }
}

// ---------------------------------------------------------------------------
// conv3: P2*W3+b3 -> relu -> pool -> per-tile channel sums (mean fused).
// R13 retile (proven correct): 256 CTAs (pooled 8x8), 128 thr, occ 4.
// ---------------------------------------------------------------------------
__global__ __launch_bounds__(128, 4) void conv3_kernel(
    const float* __restrict__ W, const float* __restrict__ bias)
{
    __shared__ __align__(16) float sIn[4][18][20];
    __shared__ __align__(16) float sW[9 * 4 * 32];
    __shared__ float sRed[32][32];

    const int b = blockIdx.z, by = blockIdx.y, bx = blockIdx.x;
    const int t = threadIdx.x;
    const int grp = t >> 5, slot = t & 31, py = slot >> 2, pxi = slot & 3;
    const int r0 = by * 16, c0 = bx * 16;

    unsigned long long acc[2][4][4];
#pragma unroll
    for (int dr = 0; dr < 2; ++dr)
#pragma unroll
        for (int dc = 0; dc < 4; ++dc)
#pragma unroll
            for (int j = 0; j < 4; ++j) acc[dr][dc][j] = 0ULL;

    for (int cc = 0; cc < 8; ++cc) {
        __syncthreads();
        for (int i = t; i < 18 * 18; i += 128) {
            int rr = i / 18, c = i - 18 * (i / 18);
            int gr = r0 + rr, gc = c0 + c;
            float4 v = make_float4(0.f, 0.f, 0.f, 0.f);
            if (gr < 62 && gc < 62)
                v = *(const float4*)(g_P2 + (((size_t)(b * 62 + gr) * 62 + gc) * 32 + cc * 4));
            sIn[0][rr][c] = v.x; sIn[1][rr][c] = v.y;
            sIn[2][rr][c] = v.z; sIn[3][rr][c] = v.w;
        }
        for (int i = t; i < 1152; i += 128) {
            int kk = i >> 7, rem = i & 127;
            int ci = rem >> 5, co = rem & 31;
            sW[i] = W[((kk * 32) + cc * 4 + ci) * 32 + co];
        }
        __syncthreads();
#pragma unroll
        for (int ci = 0; ci < 4; ++ci) {
            float v[4][6];
#pragma unroll
            for (int dr = 0; dr < 4; ++dr) {
                const float* row = &sIn[ci][2 * py + dr][4 * pxi];
                float4 f = *(const float4*)row;
                float2 g = *(const float2*)(row + 4);
                v[dr][0] = f.x; v[dr][1] = f.y; v[dr][2] = f.z;
                v[dr][3] = f.w; v[dr][4] = g.x; v[dr][5] = g.y;
            }
#pragma unroll
            for (int ky = 0; ky < 3; ++ky)
#pragma unroll
                for (int kx = 0; kx < 3; ++kx) {
                    const ulonglong2* wp = (const ulonglong2*)
                        &sW[((ky * 3 + kx) * 4 + ci) * 32 + 8 * grp];
                    ulonglong2 qa = wp[0], qb = wp[1];
#pragma unroll
                    for (int dr = 0; dr < 2; ++dr)
#pragma unroll
                        for (int dc = 0; dc < 4; ++dc) {
                            unsigned long long vv = pack2(v[ky + dr][kx + dc]);
                            ffma2(acc[dr][dc][0], vv, qa.x);
                            ffma2(acc[dr][dc][1], vv, qa.y);
                            ffma2(acc[dr][dc][2], vv, qb.x);
                            ffma2(acc[dr][dc][3], vv, qb.y);
                        }
                }
        }
    }

    const int ph = by * 8 + py;
    float csum[8];
#pragma unroll
    for (int j = 0; j < 8; ++j) csum[j] = 0.f;
#pragma unroll
    for (int s = 0; s < 2; ++s) {
        const int pw = bx * 8 + 2 * pxi + s;
        const bool valid = (ph < 30) && (pw < 30);
#pragma unroll
        for (int j = 0; j < 4; ++j) {
            float2 a0 = unpack2(acc[0][2 * s][j]);
            float2 a1 = unpack2(acc[0][2 * s + 1][j]);
            float2 a2 = unpack2(acc[1][2 * s][j]);
            float2 a3 = unpack2(acc[1][2 * s + 1][j]);
            float mlo = fmaxf(fmaxf(a0.x, a1.x), fmaxf(a2.x, a3.x));
            float mhi = fmaxf(fmaxf(a0.y, a1.y), fmaxf(a2.y, a3.y));
            float vlo = fmaxf(mlo + bias[8 * grp + 2 * j], 0.f);
            float vhi = fmaxf(mhi + bias[8 * grp + 2 * j + 1], 0.f);
            if (valid) { csum[2 * j] += vlo; csum[2 * j + 1] += vhi; }
        }
    }
    __syncthreads();
#pragma unroll
    for (int j = 0; j < 8; ++j) sRed[slot][8 * grp + j] = csum[j];
    __syncthreads();

    if (t < 32) {
        float s = 0.f;
#pragma unroll
        for (int p = 0; p < 32; ++p) s += sRed[p][t];
        g_part[b][by * 4 + bx][t] = s;
    }
}

// ============================ head / sampler ===============================
__global__ __launch_bounds__(64) void head_kernel(
    const float* __restrict__ D1, const float* __restrict__ db1,
    const float* __restrict__ D2, const float* __restrict__ db2,
    const float* __restrict__ D3, const float* __restrict__ db3)
{
    __shared__ float h0[32], h1[64], h2[32];
    const int b = blockIdx.x, t = threadIdx.x;

    if (t < 32) {
        float s = 0.f;
#pragma unroll
        for (int tile = 0; tile < 16; ++tile) s += g_part[b][tile][t];
        h0[t] = s * (1.f / 900.f);
    }
    __syncthreads();
    {
        float a = db1[t];
#pragma unroll
        for (int k = 0; k < 32; ++k) a = fmaf(h0[k], D1[k * 64 + t], a);
        h1[t] = fmaxf(a, 0.f);
    }
    __syncthreads();
    if (t < 32) {
        float a = db2[t];
#pragma unroll
        for (int k = 0; k < 64; ++k) a = fmaf(h1[k], D2[k * 32 + t], a);
        h2[t] = fmaxf(a, 0.f);
    }
    __syncthreads();
    if (t < 6) {
        float a = db3[t];
#pragma unroll
        for (int k = 0; k < 32; ++k) a = fmaf(h2[k], D3[k * 6 + t], a);
        g_theta[b * 6 + t] = a;
    }
}

__global__ __launch_bounds__(256) void sampler_kernel(
    const float* __restrict__ x, float* __restrict__ out)
{
    __shared__ float th[6];
    const int b = blockIdx.y;
    if (threadIdx.x < 6) th[threadIdx.x] = g_theta[b * 6 + threadIdx.x];
    __syncthreads();

    const int idx = blockIdx.x * 64 + (threadIdx.x >> 2);
    const int c8 = (threadIdx.x & 3) * 8;
    const int i = idx >> 8, j = idx & 255;

    const float xs = -1.f + (float)j * (2.f / 255.f);
    const float ys = -1.f + (float)i * (2.f / 255.f);
    const float xc = th[0] * xs + th[1] * ys + th[2];
    const float yc = th[3] * xs + th[4] * ys + th[5];
    const float xf = 0.5f * ((xc + 1.0f) * 254.0f);
    const float yf = 0.5f * ((yc + 1.0f) * 254.0f);

    int x0 = (int)floorf(xf), x1 = x0 + 1;
    int y0 = (int)floorf(yf), y1 = y0 + 1;
    x0 = min(max(x0, 0), 255); x1 = min(max(x1, 0), 255);
    y0 = min(max(y0, 0), 255); y1 = min(max(y1, 0), 255);

    const float x0f = (float)x0, x1f = (float)x1;
    const float y0f = (float)y0, y1f = (float)y1;
    const float wa = (x1f - xf) * (y1f - yf);
    const float wb = (x1f - xf) * (yf - y0f);
    const float wc = (xf - x0f) * (y1f - yf);
    const float wd = (xf - x0f) * (yf - y0f);

    const float* xb = x + (size_t)b * 256 * 256 * 32;
    const float* pa = xb + ((size_t)(y0 * 256 + x0) * 32 + c8);
    const float* pb = xb + ((size_t)(y1 * 256 + x0) * 32 + c8);
    const float* pc = xb + ((size_t)(y0 * 256 + x1) * 32 + c8);
    const float* pd = xb + ((size_t)(y1 * 256 + x1) * 32 + c8);
    float* po = out + ((size_t)(b * 65536 + idx) * 32 + c8);

#pragma unroll
    for (int h = 0; h < 2; ++h) {
        const float4 Ia = __ldg((const float4*)(pa + 4 * h));
        const float4 Ib = __ldg((const float4*)(pb + 4 * h));
        const float4 Ic = __ldg((const float4*)(pc + 4 * h));
        const float4 Id = __ldg((const float4*)(pd + 4 * h));
        float4 rr;
        rr.x = wa * Ia.x + wb * Ib.x + wc * Ic.x + wd * Id.x;
        rr.y = wa * Ia.y + wb * Ib.y + wc * Ic.y + wd * Id.y;
        rr.z = wa * Ia.z + wb * Ib.z + wc * Ic.z + wd * Id.z;
        rr.w = wa * Ia.w + wb * Ib.w + wc * Ic.w + wd * Id.w;
        *(float4*)(po + 4 * h) = rr;
    }
}

// ---------------------------------------------------------------------------
extern "C" void kernel_launch(void* const* d_in, const int* in_sizes, int n_in,
                              void* d_out, int out_size)
{
    const float* x   = (const float*)d_in[0];
    const float* W3  = (const float*)d_in[5];
    const float* b3  = (const float*)d_in[6];
    const float* D1  = (const float*)d_in[7];
    const float* db1 = (const float*)d_in[8];
    const float* D2  = (const float*)d_in[9];
    const float* db2 = (const float*)d_in[10];
    const float* D3  = (const float*)d_in[11];
    const float* db3 = (const float*)d_in[12];
    float* out = (float*)d_out;

    cudaMemcpyToSymbolAsync(c_W1, d_in[1], 4608 * sizeof(float), 0,
                            cudaMemcpyDeviceToDevice, 0);
    cudaMemcpyToSymbolAsync(c_b1, d_in[2], 16 * sizeof(float), 0,
                            cudaMemcpyDeviceToDevice, 0);
    cudaMemcpyToSymbolAsync(c_W2, d_in[3], 4608 * sizeof(float), 0,
                            cudaMemcpyDeviceToDevice, 0);
    cudaMemcpyToSymbolAsync(c_b2, d_in[4], 32 * sizeof(float), 0,
                            cudaMemcpyDeviceToDevice, 0);

    conv1_kernel<<<dim3(8, 8, 16), 256>>>(x);
    conv2_kernel<<<dim3(4, 8, 16), 256>>>();
    conv3_kernel<<<dim3(4, 4, 16), 128>>>(W3, b3);
    head_kernel<<<16, 64>>>(D1, db1, D2, db2, D3, db3);
    sampler_kernel<<<dim3(1024, 16), 256>>>(x, out);
}